// round 1
// baseline (speedup 1.0000x reference)
#include <cuda_runtime.h>
#include <cstdint>

// Nearest codeword on grid g_i = i - 7.5, i in [0,15]:
//   g(x) = clamp(ceil(x) - 0.5, -7.5, 7.5)   (ties at integers -> lower codeword,
//                                             matching jnp.argmax first-max rule)
//   idx  = g + 7.5
__device__ __forceinline__ void quant1(float x, float& g, float& id) {
    float q = ceilf(x) - 0.5f;
    q = fminf(fmaxf(q, -7.5f), 7.5f);
    g = q;
    id = q + 7.5f;
}

// Case A: out is one float32 buffer of 2N elems: [vals (N) | idx-as-float (N)]
__global__ void quant_kernel_f32f32(const float4* __restrict__ x,
                                    float4* __restrict__ vals,
                                    float4* __restrict__ idxf,
                                    int n4) {
    int i = blockIdx.x * blockDim.x + threadIdx.x;
    if (i >= n4) return;
    float4 v = x[i];
    float4 g, id;
    quant1(v.x, g.x, id.x);
    quant1(v.y, g.y, id.y);
    quant1(v.z, g.z, id.z);
    quant1(v.w, g.w, id.w);
    vals[i] = g;
    idxf[i] = id;
}

// Case B: out is one uint8 buffer of 5N bytes: [vals as f32 bytes (4N) | idx u8 (N)]
__global__ void quant_kernel_f32u8(const float4* __restrict__ x,
                                   float4* __restrict__ vals,
                                   uchar4* __restrict__ idxb,
                                   int n4) {
    int i = blockIdx.x * blockDim.x + threadIdx.x;
    if (i >= n4) return;
    float4 v = x[i];
    float4 g, id;
    quant1(v.x, g.x, id.x);
    quant1(v.y, g.y, id.y);
    quant1(v.z, g.z, id.z);
    quant1(v.w, g.w, id.w);
    vals[i] = g;
    idxb[i] = make_uchar4((unsigned char)id.x, (unsigned char)id.y,
                          (unsigned char)id.z, (unsigned char)id.w);
}

// Case C: out is just vals (N float32)
__global__ void quant_kernel_valsonly(const float4* __restrict__ x,
                                      float4* __restrict__ vals,
                                      int n4) {
    int i = blockIdx.x * blockDim.x + threadIdx.x;
    if (i >= n4) return;
    float4 v = x[i];
    float4 g, id;
    quant1(v.x, g.x, id.x);
    quant1(v.y, g.y, id.y);
    quant1(v.z, g.z, id.z);
    quant1(v.w, g.w, id.w);
    vals[i] = g;
}

extern "C" void kernel_launch(void* const* d_in, const int* in_sizes, int n_in,
                              void* d_out, int out_size) {
    const float* x = (const float*)d_in[0];
    int n = in_sizes[0];           // 8388608, divisible by 4
    int n4 = n >> 2;
    const int threads = 256;
    int blocks = (n4 + threads - 1) / threads;

    if (out_size == 2 * n) {
        // float32 output buffer: [vals | idx (promoted to f32)]
        float* out = (float*)d_out;
        quant_kernel_f32f32<<<blocks, threads>>>(
            (const float4*)x, (float4*)out, (float4*)(out + n), n4);
    } else if (out_size == 5 * n) {
        // uint8 output buffer: [vals as raw f32 bytes | idx u8]
        uint8_t* out = (uint8_t*)d_out;
        quant_kernel_f32u8<<<blocks, threads>>>(
            (const float4*)x, (float4*)out, (uchar4*)(out + (size_t)4 * n), n4);
    } else {
        // fallback: vals only
        quant_kernel_valsonly<<<blocks, threads>>>(
            (const float4*)x, (float4*)d_out, n4);
    }
}

// round 2
// speedup vs baseline: 1.0095x; 1.0095x over previous
#include <cuda_runtime.h>
#include <cstdint>

// Nearest codeword on grid g_i = i - 7.5, i in [0,15]:
//   g(x) = clamp(ceil(x) - 0.5, -7.5, 7.5)  (ties -> lower codeword, matches argmax)
//   idx  = g + 7.5
__device__ __forceinline__ void quant1(float x, float& g, float& id) {
    float q = ceilf(x) - 0.5f;
    q = fminf(fmaxf(q, -7.5f), 7.5f);
    g = q;
    id = q + 7.5f;
}

__device__ __forceinline__ float4 quant4_vals(float4 v, float4& id) {
    float4 g;
    quant1(v.x, g.x, id.x);
    quant1(v.y, g.y, id.y);
    quant1(v.z, g.z, id.z);
    quant1(v.w, g.w, id.w);
    return g;
}

// Each thread processes ITEMS float4s, block-strided (coalesced per access).
// Streaming cache hints: input read-once, outputs write-once -> keep out of L2 ways.
constexpr int ITEMS = 4;

__global__ void __launch_bounds__(256) quant_kernel_f32f32(
    const float4* __restrict__ x,
    float4* __restrict__ vals,
    float4* __restrict__ idxf,
    int n4) {
    int base = blockIdx.x * (blockDim.x * ITEMS) + threadIdx.x;
    int stride = blockDim.x;

    float4 v[ITEMS];
#pragma unroll
    for (int k = 0; k < ITEMS; k++) {
        int i = base + k * stride;
        if (i < n4) v[k] = __ldcs(&x[i]);
    }
#pragma unroll
    for (int k = 0; k < ITEMS; k++) {
        int i = base + k * stride;
        if (i < n4) {
            float4 id;
            float4 g = quant4_vals(v[k], id);
            __stcs(&vals[i], g);
            __stcs(&idxf[i], id);
        }
    }
}

// Fallback paths (other output layouts), kept for safety.
__global__ void quant_kernel_f32u8(const float4* __restrict__ x,
                                   float4* __restrict__ vals,
                                   uchar4* __restrict__ idxb,
                                   int n4) {
    int i = blockIdx.x * blockDim.x + threadIdx.x;
    if (i >= n4) return;
    float4 id;
    float4 g = quant4_vals(__ldcs(&x[i]), id);
    __stcs(&vals[i], g);
    idxb[i] = make_uchar4((unsigned char)id.x, (unsigned char)id.y,
                          (unsigned char)id.z, (unsigned char)id.w);
}

__global__ void quant_kernel_valsonly(const float4* __restrict__ x,
                                      float4* __restrict__ vals,
                                      int n4) {
    int i = blockIdx.x * blockDim.x + threadIdx.x;
    if (i >= n4) return;
    float4 id;
    float4 g = quant4_vals(__ldcs(&x[i]), id);
    __stcs(&vals[i], g);
}

extern "C" void kernel_launch(void* const* d_in, const int* in_sizes, int n_in,
                              void* d_out, int out_size) {
    const float* x = (const float*)d_in[0];
    int n = in_sizes[0];           // 8388608, divisible by 4
    int n4 = n >> 2;               // 2M float4s
    const int threads = 256;

    if (out_size == 2 * n) {
        float* out = (float*)d_out;
        int per_block = threads * ITEMS;
        int blocks = (n4 + per_block - 1) / per_block;   // 2048
        quant_kernel_f32f32<<<blocks, threads>>>(
            (const float4*)x, (float4*)out, (float4*)(out + n), n4);
    } else if (out_size == 5 * n) {
        uint8_t* out = (uint8_t*)d_out;
        int blocks = (n4 + threads - 1) / threads;
        quant_kernel_f32u8<<<blocks, threads>>>(
            (const float4*)x, (float4*)out, (uchar4*)(out + (size_t)4 * n), n4);
    } else {
        int blocks = (n4 + threads - 1) / threads;
        quant_kernel_valsonly<<<blocks, threads>>>(
            (const float4*)x, (float4*)d_out, n4);
    }
}